// round 11
// baseline (speedup 1.0000x reference)
#include <cuda_runtime.h>
#include <math.h>
#include <stdint.h>

#define NN   50000
#define EE   150000
#define DD   256
#define NP   768          // P columns = 3 * 256
#define SCAN_BLOCKS 49    // ceil(50000/1024)
#define MSPLIT 25088      // 196 * 128, M pipeline split point
#define C256  0.00390625f

// ------------------------ device scratch (no allocs allowed) ------------------
__device__ int   g_deg [3 * NN];
__device__ int   g_cur [3 * NN];
__device__ int   g_rs  [3 * (NN + 1)];
__device__ int   g_bsum[3 * SCAN_BLOCKS];
__device__ int   g_boff[3 * SCAN_BLOCKS];
__device__ int   g_snbr[3 * 2 * EE];

__device__ int8_t g_qShi[(size_t)NN * DD];
__device__ int8_t g_qSlo[(size_t)NN * DD];
__device__ float  g_sS  [NN];
__device__ float  g_Wa  [(size_t)NP * DD];    // fp32 [n=r*256+d][k]
__device__ int8_t g_qWahi[(size_t)NP * DD];
__device__ int8_t g_qWalo[(size_t)NP * DD];
__device__ float  g_sWa [NP];
__device__ float  g_Wv  [(size_t)DD * NP];    // fp32 [n=d][k'=r*256+k]
__device__ int8_t g_qWvhi[(size_t)DD * NP];
__device__ int8_t g_qWvlo[(size_t)DD * NP];
__device__ float  g_sWv [DD];
__device__ float  g_P   [(size_t)NN * NP];    // fp32, 153.6 MB
__device__ int8_t g_qThi[(size_t)NN * NP];
__device__ int8_t g_qTlo[(size_t)NN * NP];
__device__ float  g_sT  [NN];

// ------------------------ PTX helpers ----------------------------------------
__device__ __forceinline__ uint32_t smem_u32(const void* p) {
    return (uint32_t)__cvta_generic_to_shared(p);
}
__device__ __forceinline__ void cp16(uint32_t dst, const void* src, int srcsz) {
    asm volatile("cp.async.cg.shared.global [%0], [%1], 16, %2;"
                 :: "r"(dst), "l"(src), "r"(srcsz) : "memory");
}
#define CP_COMMIT() asm volatile("cp.async.commit_group;" ::: "memory")
#define CP_WAIT(n)  asm volatile("cp.async.wait_group %0;" :: "n"(n) : "memory")

#define LDSM4(r, addr) asm volatile( \
    "ldmatrix.sync.aligned.m8n8.x4.shared.b16 {%0,%1,%2,%3}, [%4];" \
    : "=r"((r)[0]), "=r"((r)[1]), "=r"((r)[2]), "=r"((r)[3]) : "r"(addr))

#define IMMA16832(d, a, b) asm volatile( \
    "mma.sync.aligned.m16n8k32.row.col.s32.s8.s8.s32 " \
    "{%0,%1,%2,%3}, {%4,%5,%6,%7}, {%8,%9}, {%0,%1,%2,%3};" \
    : "+r"((d)[0]), "+r"((d)[1]), "+r"((d)[2]), "+r"((d)[3]) \
    : "r"((a)[0]), "r"((a)[1]), "r"((a)[2]), "r"((a)[3]), \
      "r"((b)[0]), "r"((b)[1]))

// ------------------------ CSR build ------------------------------------------
__global__ void zero_kernel() {
    int idx = blockIdx.x * blockDim.x + threadIdx.x;
    if (idx < 3 * NN) { g_deg[idx] = 0; g_cur[idx] = 0; }
}

__global__ void degree_kernel(const int* __restrict__ e0,
                              const int* __restrict__ e1,
                              const int* __restrict__ e2) {
    int idx = blockIdx.x * blockDim.x + threadIdx.x;
    if (idx >= 3 * 2 * EE) return;
    int r = idx / (2 * EE);
    int k = idx - r * (2 * EE);
    const int* e = (r == 0) ? e0 : ((r == 1) ? e1 : e2);
    atomicAdd(&g_deg[r * NN + e[k]], 1);
}

__global__ void scan_local() {
    __shared__ int buf[1024];
    int r = blockIdx.y;
    int tid = threadIdx.x;
    int idx = blockIdx.x * 1024 + tid;
    int v = (idx < NN) ? g_deg[r * NN + idx] : 0;
    buf[tid] = v;
    __syncthreads();
    for (int off = 1; off < 1024; off <<= 1) {
        int t = (tid >= off) ? buf[tid - off] : 0;
        __syncthreads();
        buf[tid] += t;
        __syncthreads();
    }
    if (idx < NN) g_rs[r * (NN + 1) + idx] = buf[tid] - v;
    if (tid == 1023) g_bsum[r * SCAN_BLOCKS + blockIdx.x] = buf[1023];
}

__global__ void scan_bsums() {
    int r = threadIdx.x >> 5;
    int lane = threadIdx.x & 31;
    if (r >= 3) return;
    int carry = 0;
    for (int b0 = 0; b0 < SCAN_BLOCKS; b0 += 32) {
        int idx = b0 + lane;
        int orig = (idx < SCAN_BLOCKS) ? g_bsum[r * SCAN_BLOCKS + idx] : 0;
        int v = orig;
#pragma unroll
        for (int off = 1; off < 32; off <<= 1) {
            int t = __shfl_up_sync(0xFFFFFFFFu, v, off);
            if (lane >= off) v += t;
        }
        if (idx < SCAN_BLOCKS) g_boff[r * SCAN_BLOCKS + idx] = carry + v - orig;
        carry += __shfl_sync(0xFFFFFFFFu, v, 31);
    }
    if (lane == 0) g_rs[r * (NN + 1) + NN] = carry;
}

__global__ void scan_add() {
    int r = blockIdx.y;
    int idx = blockIdx.x * 1024 + threadIdx.x;
    if (idx < NN) g_rs[r * (NN + 1) + idx] += g_boff[r * SCAN_BLOCKS + blockIdx.x];
}

__global__ void fill_kernel(const int* __restrict__ e0,
                            const int* __restrict__ e1,
                            const int* __restrict__ e2) {
    int idx = blockIdx.x * blockDim.x + threadIdx.x;
    if (idx >= 3 * EE) return;
    int r = idx / EE;
    int k = idx - r * EE;
    const int* e = (r == 0) ? e0 : ((r == 1) ? e1 : e2);
    int a = e[2 * k], b = e[2 * k + 1];
    int pa = g_rs[r * (NN + 1) + a] + atomicAdd(&g_cur[r * NN + a], 1);
    g_snbr[r * 2 * EE + pa] = b;
    int pb = g_rs[r * (NN + 1) + b] + atomicAdd(&g_cur[r * NN + b], 1);
    g_snbr[r * 2 * EE + pb] = a;
}

// ------------------------ quantization ---------------------------------------
__device__ __forceinline__ int clamp127(int v) {
    return (v > 127) ? 127 : ((v < -127) ? -127 : v);
}
// x ~= s*(qh + ql/256), s = rowmax/127
__device__ __forceinline__ void q2(float x, float inv, int& qh, int& ql) {
    float u = x * inv;
    float fh = rintf(u);
    qh = (int)fh;
    ql = clamp127((int)rintf((u - fh) * 256.f));
}
__device__ __forceinline__ uint32_t pack4(int a, int b, int c, int d) {
    return (uint32_t)(a & 0xFF) | ((uint32_t)(b & 0xFF) << 8)
         | ((uint32_t)(c & 0xFF) << 16) | ((uint32_t)(d & 0xFF) << 24);
}

// generic per-row quantizer: warp per row, K % 128 == 0
__global__ void quantize_rows(const float* __restrict__ X, int8_t* __restrict__ qhi,
                              int8_t* __restrict__ qlo, float* __restrict__ scale,
                              int rows, int K) {
    int w = threadIdx.x >> 5, l = threadIdx.x & 31;
    int r = blockIdx.x * 8 + w;
    if (r >= rows) return;
    const float* xr = X + (size_t)r * K;
    float m = 0.f;
    for (int c = l * 4; c < K; c += 128) {
        float4 v = *(const float4*)(xr + c);
        m = fmaxf(m, fmaxf(fmaxf(fabsf(v.x), fabsf(v.y)),
                           fmaxf(fabsf(v.z), fabsf(v.w))));
    }
#pragma unroll
    for (int off = 16; off; off >>= 1)
        m = fmaxf(m, __shfl_xor_sync(0xFFFFFFFFu, m, off));
    float s = m * (1.f / 127.f);
    float inv = (m > 0.f) ? (127.f / m) : 0.f;
    if (l == 0) scale[r] = s;
    for (int c = l * 4; c < K; c += 128) {
        float4 v = *(const float4*)(xr + c);
        int h0, l0, h1, l1, h2, l2, h3, l3;
        q2(v.x, inv, h0, l0); q2(v.y, inv, h1, l1);
        q2(v.z, inv, h2, l2); q2(v.w, inv, h3, l3);
        *(uint32_t*)(qhi + (size_t)r * K + c) = pack4(h0, h1, h2, h3);
        *(uint32_t*)(qlo + (size_t)r * K + c) = pack4(l0, l1, l2, l3);
    }
}

// Wa[n=r*256+d][k] = A_r[k][d] = sum_j WQ_r[j][k] * WK_r[j][d]  (fp32)
__global__ void build_wa(const float* __restrict__ WQ,
                         const float* __restrict__ WK) {
    int b = blockIdx.x;            // 0..767
    int r = b >> 8;
    int k = b & 255;
    int d = threadIdx.x;           // 0..255
    const float* wq = WQ + r * 65536;
    const float* wk = WK + r * 65536;
    float acc = 0.f;
#pragma unroll 8
    for (int j = 0; j < 256; j++)
        acc += wq[j * 256 + k] * wk[j * 256 + d];
    g_Wa[(size_t)(r * 256 + d) * DD + k] = acc;
}

// Wv[n=d][k'=r*256+k] = W_r[d][k]  (fp32)
__global__ void build_wv(const float* __restrict__ W) {
    int idx = blockIdx.x * blockDim.x + threadIdx.x;
    if (idx >= DD * NP) return;
    int d  = idx / NP;
    int rk = idx - d * NP;
    int r  = rk >> 8;
    int k  = rk & 255;
    g_Wv[idx] = W[r * 65536 + d * 256 + k];
}

// ------------------------ int8 IMMA GEMM (3-stage pipeline) ------------------
// C[m, n] = sA[m]*sB[n]*((qAhi+qAlo/256)(qBhi+qBlo/256))  [drop lo*lo]
// Block 128x64, BK=64 bytes, 256 threads (8 warps as 4(m) x 2(n), warp 32x32).
#define SM_AHI 0
#define SM_ALO 8192
#define SM_BHI 16384
#define SM_BLO 20480
#define STG8   24576
#define GEMM_SMEM8 (3 * STG8)     // 73728

__global__ void __launch_bounds__(256)
imma_gemm(const int8_t* __restrict__ Ahi, const int8_t* __restrict__ Alo,
          const float* __restrict__ sA,
          const int8_t* __restrict__ Bhi, const int8_t* __restrict__ Blo,
          const float* __restrict__ sB,
          float* __restrict__ C, int mbase, int mEnd, int K, int N, int relu) {
    extern __shared__ char smem[];
    const uint32_t sbase = smem_u32(smem);
    const int t = threadIdx.x;
    const int w = t >> 5, l = t & 31;
    const int wm = (w >> 1) * 32;
    const int wn = (w & 1) * 32;
    const int bm = mbase + blockIdx.y * 128;
    const int n0 = blockIdx.x * 64;

    // stage-load assignment
    const int ar = t >> 1;               // A row 0..127
    const int br = t >> 2;               // B row 0..63
    int amrow = bm + ar;
    int av = (amrow < mEnd) ? 16 : 0;
    const int8_t* aHi = Ahi + (size_t)((amrow < mEnd) ? amrow : 0) * K;
    const int8_t* aLo = Alo + (size_t)((amrow < mEnd) ? amrow : 0) * K;
    const int8_t* bHi = Bhi + (size_t)(n0 + br) * K;
    const int8_t* bLo = Blo + (size_t)(n0 + br) * K;

    int acc1[2][4][4], acc2[2][4][4];
#pragma unroll
    for (int i = 0; i < 2; i++)
#pragma unroll
        for (int j = 0; j < 4; j++)
#pragma unroll
            for (int q = 0; q < 4; q++) { acc1[i][j][q] = 0; acc2[i][j][q] = 0; }

    auto load_stage = [&](int s, int kt) {
        uint32_t so = sbase + (uint32_t)s * STG8;
#pragma unroll
        for (int q = 0; q < 2; q++) {
            int c = (t & 1) * 2 + q;
            uint32_t sw = (uint32_t)(ar * 64 + ((c ^ ((ar >> 1) & 3)) << 4));
            cp16(so + SM_AHI + sw, aHi + kt * 64 + c * 16, av);
            cp16(so + SM_ALO + sw, aLo + kt * 64 + c * 16, av);
        }
        {
            int c = t & 3;
            uint32_t sw = (uint32_t)(br * 64 + ((c ^ ((br >> 1) & 3)) << 4));
            cp16(so + SM_BHI + sw, bHi + kt * 64 + c * 16, 16);
            cp16(so + SM_BLO + sw, bLo + kt * 64 + c * 16, 16);
        }
    };

    auto compute = [&](int s) {
        uint32_t aH = sbase + (uint32_t)s * STG8 + SM_AHI;
        uint32_t aL = sbase + (uint32_t)s * STG8 + SM_ALO;
        uint32_t bH = sbase + (uint32_t)s * STG8 + SM_BHI;
        uint32_t bL = sbase + (uint32_t)s * STG8 + SM_BLO;
#pragma unroll
        for (int ks = 0; ks < 2; ks++) {
            uint32_t Ah[2][4], Al[2][4];
#pragma unroll
            for (int im = 0; im < 2; im++) {
                int row = wm + im * 16 + (l & 15);
                int ch = ks * 2 + (l >> 4);
                uint32_t sw = (uint32_t)(row * 64 + ((ch ^ ((row >> 1) & 3)) << 4));
                LDSM4(Ah[im], aH + sw);
                LDSM4(Al[im], aL + sw);
            }
            uint32_t Bh[4][2], Bl[4][2];
#pragma unroll
            for (int p = 0; p < 2; p++) {
                int row = wn + p * 16 + (l & 7) + ((l >> 4) & 1) * 8;
                int ch = ks * 2 + ((l >> 3) & 1);
                uint32_t sw = (uint32_t)(row * 64 + ((ch ^ ((row >> 1) & 3)) << 4));
                uint32_t r4[4];
                LDSM4(r4, bH + sw);
                Bh[p * 2][0] = r4[0]; Bh[p * 2][1] = r4[1];
                Bh[p * 2 + 1][0] = r4[2]; Bh[p * 2 + 1][1] = r4[3];
                LDSM4(r4, bL + sw);
                Bl[p * 2][0] = r4[0]; Bl[p * 2][1] = r4[1];
                Bl[p * 2 + 1][0] = r4[2]; Bl[p * 2 + 1][1] = r4[3];
            }
#pragma unroll
            for (int im = 0; im < 2; im++)
#pragma unroll
                for (int in = 0; in < 4; in++) {
                    IMMA16832(acc1[im][in], Ah[im], Bh[in]);
                    IMMA16832(acc2[im][in], Ah[im], Bl[in]);
                    IMMA16832(acc2[im][in], Al[im], Bh[in]);
                }
        }
    };

    const int KT = K / 64;
    load_stage(0, 0); CP_COMMIT();
    load_stage(1, 1); CP_COMMIT();
    int s = 0;
    for (int kt = 0; kt < KT; kt++) {
        if (kt < KT - 1) { CP_WAIT(1); } else { CP_WAIT(0); }
        __syncthreads();
        if (kt + 2 < KT) {
            int s2 = s + 2; if (s2 >= 3) s2 -= 3;
            load_stage(s2, kt + 2);
            CP_COMMIT();
        }
        compute(s);
        if (++s == 3) s = 0;
    }

    // epilogue: dequant + optional relu
#pragma unroll
    for (int im = 0; im < 2; im++) {
        int r0 = bm + wm + im * 16 + (l >> 2);
        float sa0 = (r0 < mEnd) ? sA[r0] : 0.f;
        float sa1 = (r0 + 8 < mEnd) ? sA[r0 + 8] : 0.f;
#pragma unroll
        for (int in = 0; in < 4; in++) {
            int cc = n0 + wn + in * 8 + (l & 3) * 2;
            float sb0 = sB[cc], sb1 = sB[cc + 1];
            int* A1 = acc1[im][in];
            int* A2 = acc2[im][in];
            float v0 = sa0 * sb0 * ((float)A1[0] + (float)A2[0] * C256);
            float v1 = sa0 * sb1 * ((float)A1[1] + (float)A2[1] * C256);
            float v2 = sa1 * sb0 * ((float)A1[2] + (float)A2[2] * C256);
            float v3 = sa1 * sb1 * ((float)A1[3] + (float)A2[3] * C256);
            if (relu) {
                v0 = fmaxf(v0, 0.f); v1 = fmaxf(v1, 0.f);
                v2 = fmaxf(v2, 0.f); v3 = fmaxf(v3, 0.f);
            }
            if (r0 < mEnd)
                *(float2*)(C + (size_t)r0 * N + cc) = make_float2(v0, v1);
            if (r0 + 8 < mEnd)
                *(float2*)(C + (size_t)(r0 + 8) * N + cc) = make_float2(v2, v3);
        }
    }
}

// ------------------------ fused attention aggregation + quantize -------------
// Warp per node. All 3 relations kept in registers; epilogue quantizes the
// full 768-wide T row (per-row scale) and writes qThi/qTlo + sT.
__global__ __launch_bounds__(256)
void agg_kernel(const float* __restrict__ S, int nbase, int nEnd) {
    int w = threadIdx.x >> 5;
    int l = threadIdx.x & 31;
    int i = nbase + blockIdx.x * 8 + w;
    if (i >= nEnd) return;

    float4 a0[3], a1[3];
#pragma unroll
    for (int r = 0; r < 3; r++) {
        a0[r] = make_float4(0.f, 0.f, 0.f, 0.f);
        a1[r] = make_float4(0.f, 0.f, 0.f, 0.f);
    }

    for (int r = 0; r < 3; r++) {
        int start = g_rs[r * (NN + 1) + i];
        int deg   = g_rs[r * (NN + 1) + i + 1] - start;
        if (deg <= 0) continue;

        const float* Pb = g_P + (size_t)i * NP + r * 256;
        float4 p0 = *(const float4*)(Pb + 4 * l);
        float4 p1 = *(const float4*)(Pb + 128 + 4 * l);
        const int* nb = g_snbr + r * 2 * EE + start;

        float z = 0.f;
        for (int j = 0; j < deg; j++) {
            int nbr = nb[j];
            const float* Sr = S + (size_t)nbr * DD;
            float4 s0 = *(const float4*)(Sr + 4 * l);
            float4 s1 = *(const float4*)(Sr + 128 + 4 * l);
            float d = p0.x * s0.x + p0.y * s0.y + p0.z * s0.z + p0.w * s0.w
                    + p1.x * s1.x + p1.y * s1.y + p1.z * s1.z + p1.w * s1.w;
#pragma unroll
            for (int off = 16; off; off >>= 1)
                d += __shfl_xor_sync(0xFFFFFFFFu, d, off);
            float e = __expf(d * 0.125f);
            z += e;
            a0[r].x += e * s0.x; a0[r].y += e * s0.y;
            a0[r].z += e * s0.z; a0[r].w += e * s0.w;
            a1[r].x += e * s1.x; a1[r].y += e * s1.y;
            a1[r].z += e * s1.z; a1[r].w += e * s1.w;
        }
        float zi = 1.f / z;
        a0[r].x *= zi; a0[r].y *= zi; a0[r].z *= zi; a0[r].w *= zi;
        a1[r].x *= zi; a1[r].y *= zi; a1[r].z *= zi; a1[r].w *= zi;
    }

    // row max over all 768 values
    float m = 0.f;
#pragma unroll
    for (int r = 0; r < 3; r++) {
        m = fmaxf(m, fmaxf(fmaxf(fabsf(a0[r].x), fabsf(a0[r].y)),
                           fmaxf(fabsf(a0[r].z), fabsf(a0[r].w))));
        m = fmaxf(m, fmaxf(fmaxf(fabsf(a1[r].x), fabsf(a1[r].y)),
                           fmaxf(fabsf(a1[r].z), fabsf(a1[r].w))));
    }
#pragma unroll
    for (int off = 16; off; off >>= 1)
        m = fmaxf(m, __shfl_xor_sync(0xFFFFFFFFu, m, off));
    float inv = (m > 0.f) ? (127.f / m) : 0.f;
    if (l == 0) g_sT[i] = m * (1.f / 127.f);

#pragma unroll
    for (int r = 0; r < 3; r++) {
        size_t base = (size_t)i * NP + r * 256;
        int h0, q0, h1, q1, h2, q2v, h3, q3;
        q2(a0[r].x, inv, h0, q0); q2(a0[r].y, inv, h1, q1);
        q2(a0[r].z, inv, h2, q2v); q2(a0[r].w, inv, h3, q3);
        *(uint32_t*)(g_qThi + base + 4 * l) = pack4(h0, h1, h2, h3);
        *(uint32_t*)(g_qTlo + base + 4 * l) = pack4(q0, q1, q2v, q3);
        q2(a1[r].x, inv, h0, q0); q2(a1[r].y, inv, h1, q1);
        q2(a1[r].z, inv, h2, q2v); q2(a1[r].w, inv, h3, q3);
        *(uint32_t*)(g_qThi + base + 128 + 4 * l) = pack4(h0, h1, h2, h3);
        *(uint32_t*)(g_qTlo + base + 128 + 4 * l) = pack4(q0, q1, q2v, q3);
    }
}

// ------------------------ launch --------------------------------------------
extern "C" void kernel_launch(void* const* d_in, const int* in_sizes, int n_in,
                              void* d_out, int out_size) {
    const float* S  = (const float*)d_in[0];
    const int*   et = (const int*)d_in[1];
    const int*   ec = (const int*)d_in[2];
    const int*   e2 = (const int*)d_in[3];
    const float* W  = (const float*)d_in[4];
    const float* WQ = (const float*)d_in[5];
    const float* WK = (const float*)d_in[6];
    float* out = (float*)d_out;

    static bool init = false;
    static int8_t *pqShi, *pqSlo, *pqWahi, *pqWalo, *pqWvhi, *pqWvlo, *pqThi, *pqTlo;
    static float  *psS, *pWa, *psWa, *pWv, *psWv, *pP, *psT;
    static cudaStream_t s1, s2, s3;
    static cudaEvent_t evFork, evCSR, evW, evG1a, evG1b, evAa, evAb;
    if (!init) {
        cudaGetSymbolAddress((void**)&pqShi, g_qShi);
        cudaGetSymbolAddress((void**)&pqSlo, g_qSlo);
        cudaGetSymbolAddress((void**)&psS,   g_sS);
        cudaGetSymbolAddress((void**)&pWa,   g_Wa);
        cudaGetSymbolAddress((void**)&pqWahi, g_qWahi);
        cudaGetSymbolAddress((void**)&pqWalo, g_qWalo);
        cudaGetSymbolAddress((void**)&psWa,  g_sWa);
        cudaGetSymbolAddress((void**)&pWv,   g_Wv);
        cudaGetSymbolAddress((void**)&pqWvhi, g_qWvhi);
        cudaGetSymbolAddress((void**)&pqWvlo, g_qWvlo);
        cudaGetSymbolAddress((void**)&psWv,  g_sWv);
        cudaGetSymbolAddress((void**)&pP,    g_P);
        cudaGetSymbolAddress((void**)&pqThi, g_qThi);
        cudaGetSymbolAddress((void**)&pqTlo, g_qTlo);
        cudaGetSymbolAddress((void**)&psT,   g_sT);
        cudaFuncSetAttribute(imma_gemm, cudaFuncAttributeMaxDynamicSharedMemorySize,
                             GEMM_SMEM8);
        cudaStreamCreateWithFlags(&s1, cudaStreamNonBlocking);
        cudaStreamCreateWithFlags(&s2, cudaStreamNonBlocking);
        cudaStreamCreateWithFlags(&s3, cudaStreamNonBlocking);
        cudaEventCreateWithFlags(&evFork, cudaEventDisableTiming);
        cudaEventCreateWithFlags(&evCSR,  cudaEventDisableTiming);
        cudaEventCreateWithFlags(&evW,    cudaEventDisableTiming);
        cudaEventCreateWithFlags(&evG1a,  cudaEventDisableTiming);
        cudaEventCreateWithFlags(&evG1b,  cudaEventDisableTiming);
        cudaEventCreateWithFlags(&evAa,   cudaEventDisableTiming);
        cudaEventCreateWithFlags(&evAb,   cudaEventDisableTiming);
        init = true;
    }

    const int MB_A = MSPLIT / 128;                 // 196
    const int MB_B = (NN - MSPLIT + 127) / 128;    // 195
    const int NB_A = (MSPLIT + 7) / 8;
    const int NB_B = (NN - MSPLIT + 7) / 8;

    // fork
    cudaEventRecord(evFork, 0);
    cudaStreamWaitEvent(s1, evFork, 0);
    cudaStreamWaitEvent(s2, evFork, 0);
    cudaStreamWaitEvent(s3, evFork, 0);

    // s1: CSR build chain
    zero_kernel<<<(3 * NN + 255) / 256, 256, 0, s1>>>();
    degree_kernel<<<(3 * 2 * EE + 255) / 256, 256, 0, s1>>>(et, ec, e2);
    scan_local<<<dim3(SCAN_BLOCKS, 3), 1024, 0, s1>>>();
    scan_bsums<<<1, 96, 0, s1>>>();
    scan_add<<<dim3(SCAN_BLOCKS, 3), 1024, 0, s1>>>();
    fill_kernel<<<(3 * EE + 255) / 256, 256, 0, s1>>>(et, ec, e2);
    cudaEventRecord(evCSR, s1);

    // s2: weight prep + quantize
    build_wa<<<NP, 256, 0, s2>>>(WQ, WK);
    build_wv<<<(DD * NP + 255) / 256, 256, 0, s2>>>(W);
    quantize_rows<<<(NP + 7) / 8, 256, 0, s2>>>(pWa, pqWahi, pqWalo, psWa, NP, DD);
    quantize_rows<<<(DD + 7) / 8, 256, 0, s2>>>(pWv, pqWvhi, pqWvlo, psWv, DD, NP);
    cudaEventRecord(evW, s2);

    // main: quantize S, then GEMM1 in two M-slices
    quantize_rows<<<(NN + 7) / 8, 256>>>(S, pqShi, pqSlo, psS, NN, DD);
    cudaStreamWaitEvent(0, evW, 0);
    imma_gemm<<<dim3(NP / 64, MB_A), 256, GEMM_SMEM8>>>(
        pqShi, pqSlo, psS, pqWahi, pqWalo, psWa, pP, 0, MSPLIT, DD, NP, 0);
    cudaEventRecord(evG1a, 0);
    imma_gemm<<<dim3(NP / 64, MB_B), 256, GEMM_SMEM8>>>(
        pqShi, pqSlo, psS, pqWahi, pqWalo, psWa, pP, MSPLIT, NN, DD, NP, 0);
    cudaEventRecord(evG1b, 0);

    // s3: agg slices overlap with GEMM1b / GEMM2a
    cudaStreamWaitEvent(s3, evCSR, 0);
    cudaStreamWaitEvent(s3, evG1a, 0);
    agg_kernel<<<NB_A, 256, 0, s3>>>(S, 0, MSPLIT);
    cudaEventRecord(evAa, s3);
    cudaStreamWaitEvent(s3, evG1b, 0);
    agg_kernel<<<NB_B, 256, 0, s3>>>(S, MSPLIT, NN);
    cudaEventRecord(evAb, s3);

    // main: GEMM2 slices (relu fused)
    cudaStreamWaitEvent(0, evAa, 0);
    imma_gemm<<<dim3(DD / 64, MB_A), 256, GEMM_SMEM8>>>(
        pqThi, pqTlo, psT, pqWvhi, pqWvlo, psWv, out, 0, MSPLIT, NP, DD, 1);
    cudaStreamWaitEvent(0, evAb, 0);
    imma_gemm<<<dim3(DD / 64, MB_B), 256, GEMM_SMEM8>>>(
        pqThi, pqTlo, psT, pqWvhi, pqWvlo, psWv, out, MSPLIT, NN, NP, DD, 1);
}

// round 12
// speedup vs baseline: 2.0487x; 2.0487x over previous
#include <cuda_runtime.h>
#include <cuda_fp16.h>
#include <math.h>
#include <stdint.h>

#define NN   50000
#define EE   150000
#define DD   256
#define NP   768          // P columns = 3 * 256
#define SCAN_BLOCKS 49    // ceil(50000/1024)
#define MSPLIT 25088      // 196 * 128, M pipeline split point

// ------------------------ device scratch (no allocs allowed) ------------------
__device__ int   g_deg [3 * NN];
__device__ int   g_cur [3 * NN];
__device__ int   g_rs  [3 * (NN + 1)];
__device__ int   g_bsum[3 * SCAN_BLOCKS];
__device__ int   g_boff[3 * SCAN_BLOCKS];
__device__ int   g_snbr[3 * 2 * EE];

__device__ __half g_Shi[(size_t)NN * DD];
__device__ __half g_Slo[(size_t)NN * DD];
__device__ __half g_Wahi[(size_t)NP * DD];   // [n=r*256+d][k], hi only
__device__ __half g_Wvhi[(size_t)DD * NP];   // [n=d][k'=r*256+k], hi only
__device__ float  g_P  [(size_t)NN * NP];    // 153.6 MB
__device__ __half g_Thi[(size_t)NN * NP];
__device__ __half g_Tlo[(size_t)NN * NP];

// ------------------------ PTX helpers ----------------------------------------
__device__ __forceinline__ uint32_t smem_u32(const void* p) {
    return (uint32_t)__cvta_generic_to_shared(p);
}
__device__ __forceinline__ void cp16(uint32_t dst, const void* src, int srcsz) {
    asm volatile("cp.async.cg.shared.global [%0], [%1], 16, %2;"
                 :: "r"(dst), "l"(src), "r"(srcsz) : "memory");
}
#define CP_COMMIT() asm volatile("cp.async.commit_group;" ::: "memory")
#define CP_WAIT(n)  asm volatile("cp.async.wait_group %0;" :: "n"(n) : "memory")

#define LDSM4(r, addr) asm volatile( \
    "ldmatrix.sync.aligned.m8n8.x4.shared.b16 {%0,%1,%2,%3}, [%4];" \
    : "=r"((r)[0]), "=r"((r)[1]), "=r"((r)[2]), "=r"((r)[3]) : "r"(addr))

#define MMA16816H(d, a, b) asm volatile( \
    "mma.sync.aligned.m16n8k16.row.col.f32.f16.f16.f32 " \
    "{%0,%1,%2,%3}, {%4,%5,%6,%7}, {%8,%9}, {%0,%1,%2,%3};" \
    : "+f"((d)[0]), "+f"((d)[1]), "+f"((d)[2]), "+f"((d)[3]) \
    : "r"((a)[0]), "r"((a)[1]), "r"((a)[2]), "r"((a)[3]), \
      "r"((b)[0]), "r"((b)[1]))

// ------------------------ CSR build ------------------------------------------
__global__ void zero_kernel() {
    int idx = blockIdx.x * blockDim.x + threadIdx.x;
    if (idx < 3 * NN) { g_deg[idx] = 0; g_cur[idx] = 0; }
}

__global__ void degree_kernel(const int* __restrict__ e0,
                              const int* __restrict__ e1,
                              const int* __restrict__ e2) {
    int idx = blockIdx.x * blockDim.x + threadIdx.x;
    if (idx >= 3 * 2 * EE) return;
    int r = idx / (2 * EE);
    int k = idx - r * (2 * EE);
    const int* e = (r == 0) ? e0 : ((r == 1) ? e1 : e2);
    atomicAdd(&g_deg[r * NN + e[k]], 1);
}

__global__ void scan_local() {
    __shared__ int buf[1024];
    int r = blockIdx.y;
    int tid = threadIdx.x;
    int idx = blockIdx.x * 1024 + tid;
    int v = (idx < NN) ? g_deg[r * NN + idx] : 0;
    buf[tid] = v;
    __syncthreads();
    for (int off = 1; off < 1024; off <<= 1) {
        int t = (tid >= off) ? buf[tid - off] : 0;
        __syncthreads();
        buf[tid] += t;
        __syncthreads();
    }
    if (idx < NN) g_rs[r * (NN + 1) + idx] = buf[tid] - v;
    if (tid == 1023) g_bsum[r * SCAN_BLOCKS + blockIdx.x] = buf[1023];
}

__global__ void scan_bsums() {
    int r = threadIdx.x >> 5;
    int lane = threadIdx.x & 31;
    if (r >= 3) return;
    int carry = 0;
    for (int b0 = 0; b0 < SCAN_BLOCKS; b0 += 32) {
        int idx = b0 + lane;
        int orig = (idx < SCAN_BLOCKS) ? g_bsum[r * SCAN_BLOCKS + idx] : 0;
        int v = orig;
#pragma unroll
        for (int off = 1; off < 32; off <<= 1) {
            int t = __shfl_up_sync(0xFFFFFFFFu, v, off);
            if (lane >= off) v += t;
        }
        if (idx < SCAN_BLOCKS) g_boff[r * SCAN_BLOCKS + idx] = carry + v - orig;
        carry += __shfl_sync(0xFFFFFFFFu, v, 31);
    }
    if (lane == 0) g_rs[r * (NN + 1) + NN] = carry;
}

__global__ void scan_add() {
    int r = blockIdx.y;
    int idx = blockIdx.x * 1024 + threadIdx.x;
    if (idx < NN) g_rs[r * (NN + 1) + idx] += g_boff[r * SCAN_BLOCKS + blockIdx.x];
}

__global__ void fill_kernel(const int* __restrict__ e0,
                            const int* __restrict__ e1,
                            const int* __restrict__ e2) {
    int idx = blockIdx.x * blockDim.x + threadIdx.x;
    if (idx >= 3 * EE) return;
    int r = idx / EE;
    int k = idx - r * EE;
    const int* e = (r == 0) ? e0 : ((r == 1) ? e1 : e2);
    int a = e[2 * k], b = e[2 * k + 1];
    int pa = g_rs[r * (NN + 1) + a] + atomicAdd(&g_cur[r * NN + a], 1);
    g_snbr[r * 2 * EE + pa] = b;
    int pb = g_rs[r * (NN + 1) + b] + atomicAdd(&g_cur[r * NN + b], 1);
    g_snbr[r * 2 * EE + pb] = a;
}

// ------------------------ fp16 hi/lo conversions -----------------------------
__device__ __forceinline__ void split4h(float4 v, __half* hp, __half* lp) {
    __half h0 = __float2half(v.x), h1 = __float2half(v.y);
    __half h2 = __float2half(v.z), h3 = __float2half(v.w);
    __half l0 = __float2half(v.x - __half2float(h0));
    __half l1 = __float2half(v.y - __half2float(h1));
    __half l2 = __float2half(v.z - __half2float(h2));
    __half l3 = __float2half(v.w - __half2float(h3));
    ((__half2*)hp)[0] = __halves2half2(h0, h1);
    ((__half2*)hp)[1] = __halves2half2(h2, h3);
    ((__half2*)lp)[0] = __halves2half2(l0, l1);
    ((__half2*)lp)[1] = __halves2half2(l2, l3);
}

__global__ void convertS_kernel(const float* __restrict__ S) {
    int idx = blockIdx.x * blockDim.x + threadIdx.x;      // float4 index
    if (idx >= NN * DD / 4) return;
    float4 v = ((const float4*)S)[idx];
    split4h(v, g_Shi + idx * 4, g_Slo + idx * 4);
}

// Wa[n=r*256+d][k] = A_r[k][d] = sum_j WQ_r[j][k] * WK_r[j][d]  (fp16 hi only)
__global__ void build_wa(const float* __restrict__ WQ,
                         const float* __restrict__ WK) {
    int b = blockIdx.x;            // 0..767
    int r = b >> 8;
    int k = b & 255;
    int d = threadIdx.x;           // 0..255
    const float* wq = WQ + r * 65536;
    const float* wk = WK + r * 65536;
    float acc = 0.f;
#pragma unroll 8
    for (int j = 0; j < 256; j++)
        acc += wq[j * 256 + k] * wk[j * 256 + d];
    g_Wahi[(size_t)(r * 256 + d) * DD + k] = __float2half(acc);
}

// Wv[n=d][k'=r*256+k] = W_r[d][k]  (fp16 hi only)
__global__ void build_wv(const float* __restrict__ W) {
    int idx = blockIdx.x * blockDim.x + threadIdx.x;
    if (idx >= DD * NP) return;
    int d  = idx / NP;
    int rk = idx - d * NP;
    int r  = rk >> 8;
    int k  = rk & 255;
    g_Wvhi[idx] = __float2half(W[r * 65536 + d * 256 + k]);
}

// ------------------------ mma.sync fp16 2-product GEMM -----------------------
// C = (Ah + Al) @ Bh^T; A split is exact, error = B rounding only (~1.4e-4).
// BM=128, BN=128, BK=32, 256 threads (2x4 warps, warp tile 64x32), 3 stages.
#define STG      32768                  // per-stage: A(hi|lo) 16K | B(hi) 16K
#define GEMM_SMEM (3 * STG)

__global__ void __launch_bounds__(256)
mma_gemm(const __half* __restrict__ Ahi, const __half* __restrict__ Alo,
         const __half* __restrict__ Bhi,
         float* __restrict__ C, int mbase, int mEnd, int K, int N, int relu) {
    extern __shared__ char smem[];
    const uint32_t sbase = smem_u32(smem);
    const int t = threadIdx.x;
    const int w = t >> 5, l = t & 31;
    const int wm = (w >> 2) * 64;
    const int wn = (w & 3) * 32;
    const int bm = mbase + blockIdx.y * 128;
    const int n0 = blockIdx.x * 128;

    const int lrow = t >> 1;
    const int half = t & 1;
    const __half* aRow = (half ? Alo : Ahi);
    int mrow = bm + lrow;
    int av = (mrow < mEnd) ? 16 : 0;
    aRow += (size_t)((mrow < mEnd) ? mrow : 0) * K;
    const __half* bRow = Bhi + (size_t)(n0 + lrow) * K;
    const uint32_t aDst = sbase + lrow * 128;
    const uint32_t bDst = sbase + 16384 + lrow * 128;

    float acc[4][4][4];
#pragma unroll
    for (int i = 0; i < 4; i++)
#pragma unroll
        for (int j = 0; j < 4; j++)
#pragma unroll
            for (int q = 0; q < 4; q++) acc[i][j][q] = 0.f;

    auto load_stage = [&](int s, int kt) {
        uint32_t so = (uint32_t)s * STG;
        // A: 4 chunks (hi at 0-3 / lo at 4-7 within the 128B row)
#pragma unroll
        for (int c = 0; c < 4; c++) {
            int chunk = half * 4 + c;
            uint32_t sw = (uint32_t)((chunk ^ (lrow & 7)) << 4);
            cp16(aDst + so + sw, aRow + kt * 32 + c * 8, av);
        }
        // B: hi only, chunks 0-3 split across the two half-threads
#pragma unroll
        for (int q = 0; q < 2; q++) {
            int cb = half * 2 + q;
            uint32_t sw = (uint32_t)((cb ^ (lrow & 7)) << 4);
            cp16(bDst + so + sw, bRow + kt * 32 + cb * 8, 16);
        }
    };

    auto compute = [&](int s) {
        uint32_t aB = sbase + (uint32_t)s * STG;
        uint32_t bB = aB + 16384;
#pragma unroll
        for (int ks = 0; ks < 2; ks++) {
            uint32_t Af[2][4][4];
#pragma unroll
            for (int im = 0; im < 4; im++) {
                int row = wm + im * 16 + (l & 15);
                int ch = ks * 2 + (l >> 4);
                LDSM4(Af[0][im], aB + row * 128 + ((ch ^ (row & 7)) << 4));
                LDSM4(Af[1][im], aB + row * 128 + (((ch + 4) ^ (row & 7)) << 4));
            }
            uint32_t Bf[4][2];
#pragma unroll
            for (int p = 0; p < 2; p++) {
                int row = wn + p * 16 + (l & 7) + ((l >> 4) & 1) * 8;
                int ch = ks * 2 + ((l >> 3) & 1);
                uint32_t r4[4];
                LDSM4(r4, bB + row * 128 + ((ch ^ (row & 7)) << 4));
                Bf[p * 2][0] = r4[0]; Bf[p * 2][1] = r4[1];
                Bf[p * 2 + 1][0] = r4[2]; Bf[p * 2 + 1][1] = r4[3];
            }
#pragma unroll
            for (int im = 0; im < 4; im++)
#pragma unroll
                for (int in = 0; in < 4; in++)
                    MMA16816H(acc[im][in], Af[0][im], Bf[in]);
#pragma unroll
            for (int im = 0; im < 4; im++)
#pragma unroll
                for (int in = 0; in < 4; in++)
                    MMA16816H(acc[im][in], Af[1][im], Bf[in]);
        }
    };

    const int KT = K / 32;
    load_stage(0, 0); CP_COMMIT();
    load_stage(1, 1); CP_COMMIT();
    int s = 0;
    for (int kt = 0; kt < KT; kt++) {
        if (kt < KT - 1) { CP_WAIT(1); } else { CP_WAIT(0); }
        __syncthreads();
        if (kt + 2 < KT) {
            int s2 = s + 2; if (s2 >= 3) s2 -= 3;
            load_stage(s2, kt + 2);
            CP_COMMIT();
        }
        compute(s);
        if (++s == 3) s = 0;
    }

#pragma unroll
    for (int im = 0; im < 4; im++) {
        int r0 = bm + wm + im * 16 + (l >> 2);
#pragma unroll
        for (int in = 0; in < 4; in++) {
            int cc = n0 + wn + in * 8 + (l & 3) * 2;
            float* a4 = acc[im][in];
            if (relu) {
                a4[0] = fmaxf(a4[0], 0.f); a4[1] = fmaxf(a4[1], 0.f);
                a4[2] = fmaxf(a4[2], 0.f); a4[3] = fmaxf(a4[3], 0.f);
            }
            if (r0 < mEnd)
                *(float2*)(C + (size_t)r0 * N + cc) = make_float2(a4[0], a4[1]);
            if (r0 + 8 < mEnd)
                *(float2*)(C + (size_t)(r0 + 8) * N + cc) = make_float2(a4[2], a4[3]);
        }
    }
}

// ------------------------ fused attention aggregation (single pass) ----------
__global__ __launch_bounds__(256)
void agg_kernel(const float* __restrict__ S, int nbase, int nEnd) {
    int w = threadIdx.x >> 5;
    int l = threadIdx.x & 31;
    int i = nbase + blockIdx.x * 8 + w;
    if (i >= nEnd) return;

    for (int r = 0; r < 3; r++) {
        float4 acc0 = make_float4(0.f, 0.f, 0.f, 0.f);
        float4 acc1 = make_float4(0.f, 0.f, 0.f, 0.f);
        int start = g_rs[r * (NN + 1) + i];
        int deg   = g_rs[r * (NN + 1) + i + 1] - start;

        if (deg > 0) {
            const float* Pb = g_P + (size_t)i * NP + r * 256;
            float4 p0 = *(const float4*)(Pb + 4 * l);
            float4 p1 = *(const float4*)(Pb + 128 + 4 * l);
            const int* nb = g_snbr + r * 2 * EE + start;

            float z = 0.f;
            for (int j = 0; j < deg; j++) {
                int nbr = nb[j];
                const float* Sr = S + (size_t)nbr * DD;
                float4 s0 = *(const float4*)(Sr + 4 * l);
                float4 s1 = *(const float4*)(Sr + 128 + 4 * l);
                float d = p0.x * s0.x + p0.y * s0.y + p0.z * s0.z + p0.w * s0.w
                        + p1.x * s1.x + p1.y * s1.y + p1.z * s1.z + p1.w * s1.w;
#pragma unroll
                for (int off = 16; off; off >>= 1)
                    d += __shfl_xor_sync(0xFFFFFFFFu, d, off);
                float e = __expf(d * 0.125f);
                z += e;
                acc0.x += e * s0.x; acc0.y += e * s0.y;
                acc0.z += e * s0.z; acc0.w += e * s0.w;
                acc1.x += e * s1.x; acc1.y += e * s1.y;
                acc1.z += e * s1.z; acc1.w += e * s1.w;
            }
            float zi = 1.f / z;
            acc0.x *= zi; acc0.y *= zi; acc0.z *= zi; acc0.w *= zi;
            acc1.x *= zi; acc1.y *= zi; acc1.z *= zi; acc1.w *= zi;
        }
        size_t base = (size_t)i * NP + r * 256;
        split4h(acc0, g_Thi + base + 4 * l,       g_Tlo + base + 4 * l);
        split4h(acc1, g_Thi + base + 128 + 4 * l, g_Tlo + base + 128 + 4 * l);
    }
}

// ------------------------ launch --------------------------------------------
extern "C" void kernel_launch(void* const* d_in, const int* in_sizes, int n_in,
                              void* d_out, int out_size) {
    const float* S  = (const float*)d_in[0];
    const int*   et = (const int*)d_in[1];
    const int*   ec = (const int*)d_in[2];
    const int*   e2 = (const int*)d_in[3];
    const float* W  = (const float*)d_in[4];
    const float* WQ = (const float*)d_in[5];
    const float* WK = (const float*)d_in[6];
    float* out = (float*)d_out;

    static bool init = false;
    static __half *pShi, *pSlo, *pWahi, *pWvhi, *pThi, *pTlo;
    static float* pP;
    static cudaStream_t s1, s2, s3;
    static cudaEvent_t evFork, evCSR, evW, evG1a, evG1b, evAa, evAb;
    if (!init) {
        cudaGetSymbolAddress((void**)&pShi,  g_Shi);
        cudaGetSymbolAddress((void**)&pSlo,  g_Slo);
        cudaGetSymbolAddress((void**)&pWahi, g_Wahi);
        cudaGetSymbolAddress((void**)&pWvhi, g_Wvhi);
        cudaGetSymbolAddress((void**)&pThi,  g_Thi);
        cudaGetSymbolAddress((void**)&pTlo,  g_Tlo);
        cudaGetSymbolAddress((void**)&pP,    g_P);
        cudaFuncSetAttribute(mma_gemm, cudaFuncAttributeMaxDynamicSharedMemorySize,
                             GEMM_SMEM);
        cudaStreamCreateWithFlags(&s1, cudaStreamNonBlocking);
        cudaStreamCreateWithFlags(&s2, cudaStreamNonBlocking);
        cudaStreamCreateWithFlags(&s3, cudaStreamNonBlocking);
        cudaEventCreateWithFlags(&evFork, cudaEventDisableTiming);
        cudaEventCreateWithFlags(&evCSR,  cudaEventDisableTiming);
        cudaEventCreateWithFlags(&evW,    cudaEventDisableTiming);
        cudaEventCreateWithFlags(&evG1a,  cudaEventDisableTiming);
        cudaEventCreateWithFlags(&evG1b,  cudaEventDisableTiming);
        cudaEventCreateWithFlags(&evAa,   cudaEventDisableTiming);
        cudaEventCreateWithFlags(&evAb,   cudaEventDisableTiming);
        init = true;
    }

    const int MB_A = MSPLIT / 128;                 // 196
    const int MB_B = (NN - MSPLIT + 127) / 128;    // 195
    const int NB_A = (MSPLIT + 7) / 8;
    const int NB_B = (NN - MSPLIT + 7) / 8;

    // fork
    cudaEventRecord(evFork, 0);
    cudaStreamWaitEvent(s1, evFork, 0);
    cudaStreamWaitEvent(s2, evFork, 0);
    cudaStreamWaitEvent(s3, evFork, 0);

    // s1: CSR build chain
    zero_kernel<<<(3 * NN + 255) / 256, 256, 0, s1>>>();
    degree_kernel<<<(3 * 2 * EE + 255) / 256, 256, 0, s1>>>(et, ec, e2);
    scan_local<<<dim3(SCAN_BLOCKS, 3), 1024, 0, s1>>>();
    scan_bsums<<<1, 96, 0, s1>>>();
    scan_add<<<dim3(SCAN_BLOCKS, 3), 1024, 0, s1>>>();
    fill_kernel<<<(3 * EE + 255) / 256, 256, 0, s1>>>(et, ec, e2);
    cudaEventRecord(evCSR, s1);

    // s2: weight prep
    build_wa<<<NP, 256, 0, s2>>>(WQ, WK);
    build_wv<<<(DD * NP + 255) / 256, 256, 0, s2>>>(W);
    cudaEventRecord(evW, s2);

    // main: convert S, then GEMM1 in two M-slices
    convertS_kernel<<<(NN * DD / 4 + 255) / 256, 256>>>(S);
    cudaStreamWaitEvent(0, evW, 0);
    mma_gemm<<<dim3(NP / 128, MB_A), 256, GEMM_SMEM>>>(
        pShi, pSlo, pWahi, pP, 0, MSPLIT, DD, NP, 0);
    cudaEventRecord(evG1a, 0);
    mma_gemm<<<dim3(NP / 128, MB_B), 256, GEMM_SMEM>>>(
        pShi, pSlo, pWahi, pP, MSPLIT, NN, DD, NP, 0);
    cudaEventRecord(evG1b, 0);

    // s3: agg slices (overlap with GEMM1b / GEMM2a)
    cudaStreamWaitEvent(s3, evCSR, 0);
    cudaStreamWaitEvent(s3, evG1a, 0);
    agg_kernel<<<NB_A, 256, 0, s3>>>(S, 0, MSPLIT);
    cudaEventRecord(evAa, s3);
    cudaStreamWaitEvent(s3, evG1b, 0);
    agg_kernel<<<NB_B, 256, 0, s3>>>(S, MSPLIT, NN);
    cudaEventRecord(evAb, s3);

    // main: GEMM2 slices (relu fused)
    cudaStreamWaitEvent(0, evAa, 0);
    mma_gemm<<<dim3(DD / 128, MB_A), 256, GEMM_SMEM>>>(
        pThi, pTlo, pWvhi, out, 0, MSPLIT, NP, DD, 1);
    cudaStreamWaitEvent(0, evAb, 0);
    mma_gemm<<<dim3(DD / 128, MB_B), 256, GEMM_SMEM>>>(
        pThi, pTlo, pWvhi, out, MSPLIT, NN, NP, DD, 1);
}

// round 13
// speedup vs baseline: 2.9519x; 1.4408x over previous
#include <cuda_runtime.h>
#include <cuda_fp16.h>
#include <math.h>
#include <stdint.h>

#define NN   50000
#define EE   150000
#define DD   256
#define NP   768          // P columns = 3 * 256
#define SCAN_BLOCKS 49    // ceil(50000/1024)
#define MSPLIT 25088      // 196 * 128, M pipeline split point

// ------------------------ device scratch (no allocs allowed) ------------------
__device__ int   g_deg [3 * NN];
__device__ int   g_cur [3 * NN];
__device__ int   g_rs  [3 * (NN + 1)];
__device__ int   g_bsum[3 * SCAN_BLOCKS];
__device__ int   g_boff[3 * SCAN_BLOCKS];
__device__ int   g_snbr[3 * 2 * EE];

__device__ __half g_Sh [(size_t)NN * DD];
__device__ __half g_Wah[(size_t)NP * DD];   // [n=r*256+d][k]
__device__ __half g_Wvh[(size_t)DD * NP];   // [n=d][k'=r*256+k]
__device__ float  g_P  [(size_t)NN * NP];   // 153.6 MB
__device__ __half g_Th [(size_t)NN * NP];

// ------------------------ PTX helpers ----------------------------------------
__device__ __forceinline__ uint32_t smem_u32(const void* p) {
    return (uint32_t)__cvta_generic_to_shared(p);
}
__device__ __forceinline__ void cp16(uint32_t dst, const void* src, int srcsz) {
    asm volatile("cp.async.cg.shared.global [%0], [%1], 16, %2;"
                 :: "r"(dst), "l"(src), "r"(srcsz) : "memory");
}
#define CP_COMMIT() asm volatile("cp.async.commit_group;" ::: "memory")
#define CP_WAIT(n)  asm volatile("cp.async.wait_group %0;" :: "n"(n) : "memory")

#define LDSM4(r, addr) asm volatile( \
    "ldmatrix.sync.aligned.m8n8.x4.shared.b16 {%0,%1,%2,%3}, [%4];" \
    : "=r"((r)[0]), "=r"((r)[1]), "=r"((r)[2]), "=r"((r)[3]) : "r"(addr))

#define MMA16816H(d, a, b) asm volatile( \
    "mma.sync.aligned.m16n8k16.row.col.f32.f16.f16.f32 " \
    "{%0,%1,%2,%3}, {%4,%5,%6,%7}, {%8,%9}, {%0,%1,%2,%3};" \
    : "+f"((d)[0]), "+f"((d)[1]), "+f"((d)[2]), "+f"((d)[3]) \
    : "r"((a)[0]), "r"((a)[1]), "r"((a)[2]), "r"((a)[3]), \
      "r"((b)[0]), "r"((b)[1]))

// ------------------------ CSR build ------------------------------------------
__global__ void zero_kernel() {
    int idx = blockIdx.x * blockDim.x + threadIdx.x;
    if (idx < 3 * NN) { g_deg[idx] = 0; g_cur[idx] = 0; }
}

__global__ void degree_kernel(const int* __restrict__ e0,
                              const int* __restrict__ e1,
                              const int* __restrict__ e2) {
    int idx = blockIdx.x * blockDim.x + threadIdx.x;
    if (idx >= 3 * 2 * EE) return;
    int r = idx / (2 * EE);
    int k = idx - r * (2 * EE);
    const int* e = (r == 0) ? e0 : ((r == 1) ? e1 : e2);
    atomicAdd(&g_deg[r * NN + e[k]], 1);
}

__global__ void scan_local() {
    __shared__ int buf[1024];
    int r = blockIdx.y;
    int tid = threadIdx.x;
    int idx = blockIdx.x * 1024 + tid;
    int v = (idx < NN) ? g_deg[r * NN + idx] : 0;
    buf[tid] = v;
    __syncthreads();
    for (int off = 1; off < 1024; off <<= 1) {
        int t = (tid >= off) ? buf[tid - off] : 0;
        __syncthreads();
        buf[tid] += t;
        __syncthreads();
    }
    if (idx < NN) g_rs[r * (NN + 1) + idx] = buf[tid] - v;
    if (tid == 1023) g_bsum[r * SCAN_BLOCKS + blockIdx.x] = buf[1023];
}

__global__ void scan_bsums() {
    int r = threadIdx.x >> 5;
    int lane = threadIdx.x & 31;
    if (r >= 3) return;
    int carry = 0;
    for (int b0 = 0; b0 < SCAN_BLOCKS; b0 += 32) {
        int idx = b0 + lane;
        int orig = (idx < SCAN_BLOCKS) ? g_bsum[r * SCAN_BLOCKS + idx] : 0;
        int v = orig;
#pragma unroll
        for (int off = 1; off < 32; off <<= 1) {
            int t = __shfl_up_sync(0xFFFFFFFFu, v, off);
            if (lane >= off) v += t;
        }
        if (idx < SCAN_BLOCKS) g_boff[r * SCAN_BLOCKS + idx] = carry + v - orig;
        carry += __shfl_sync(0xFFFFFFFFu, v, 31);
    }
    if (lane == 0) g_rs[r * (NN + 1) + NN] = carry;
}

__global__ void scan_add() {
    int r = blockIdx.y;
    int idx = blockIdx.x * 1024 + threadIdx.x;
    if (idx < NN) g_rs[r * (NN + 1) + idx] += g_boff[r * SCAN_BLOCKS + blockIdx.x];
}

__global__ void fill_kernel(const int* __restrict__ e0,
                            const int* __restrict__ e1,
                            const int* __restrict__ e2) {
    int idx = blockIdx.x * blockDim.x + threadIdx.x;
    if (idx >= 3 * EE) return;
    int r = idx / EE;
    int k = idx - r * EE;
    const int* e = (r == 0) ? e0 : ((r == 1) ? e1 : e2);
    int a = e[2 * k], b = e[2 * k + 1];
    int pa = g_rs[r * (NN + 1) + a] + atomicAdd(&g_cur[r * NN + a], 1);
    g_snbr[r * 2 * EE + pa] = b;
    int pb = g_rs[r * (NN + 1) + b] + atomicAdd(&g_cur[r * NN + b], 1);
    g_snbr[r * 2 * EE + pb] = a;
}

// ------------------------ conversions ----------------------------------------
__device__ __forceinline__ void cvt4h(float4 v, __half* hp) {
    ((__half2*)hp)[0] = __halves2half2(__float2half(v.x), __float2half(v.y));
    ((__half2*)hp)[1] = __halves2half2(__float2half(v.z), __float2half(v.w));
}

__global__ void convertS_kernel(const float* __restrict__ S) {
    int idx = blockIdx.x * blockDim.x + threadIdx.x;      // float4 index
    if (idx >= NN * DD / 4) return;
    float4 v = ((const float4*)S)[idx];
    cvt4h(v, g_Sh + idx * 4);
}

// Wa[n=r*256+d][k] = A_r[k][d] = sum_j WQ_r[j][k] * WK_r[j][d]
__global__ void build_wa(const float* __restrict__ WQ,
                         const float* __restrict__ WK) {
    int b = blockIdx.x;            // 0..767
    int r = b >> 8;
    int k = b & 255;
    int d = threadIdx.x;           // 0..255
    const float* wq = WQ + r * 65536;
    const float* wk = WK + r * 65536;
    float acc = 0.f;
#pragma unroll 8
    for (int j = 0; j < 256; j++)
        acc += wq[j * 256 + k] * wk[j * 256 + d];
    g_Wah[(size_t)(r * 256 + d) * DD + k] = __float2half(acc);
}

// Wv[n=d][k'=r*256+k] = W_r[d][k]
__global__ void build_wv(const float* __restrict__ W) {
    int idx = blockIdx.x * blockDim.x + threadIdx.x;
    if (idx >= DD * NP) return;
    int d  = idx / NP;
    int rk = idx - d * NP;
    int r  = rk >> 8;
    int k  = rk & 255;
    g_Wvh[idx] = __float2half(W[r * 65536 + d * 256 + k]);
}

// ------------------------ mma.sync fp16 single-product GEMM ------------------
// C = A @ B^T, fp16 inputs, fp32 accum. BM=128, BN=128, BK=64, 256 threads
// (2x4 warps, warp tile 64x32), 3-stage cp.async pipeline, SW128-style swizzle.
#define STG      32768                  // per-stage: A 16K | B 16K (128 rows x 128B)
#define GEMM_SMEM (3 * STG)

__global__ void __launch_bounds__(256)
mma_gemm(const __half* __restrict__ A, const __half* __restrict__ B,
         float* __restrict__ C, int mbase, int mEnd, int K, int N, int relu) {
    extern __shared__ char smem[];
    const uint32_t sbase = smem_u32(smem);
    const int t = threadIdx.x;
    const int w = t >> 5, l = t & 31;
    const int wm = (w >> 2) * 64;
    const int wn = (w & 3) * 32;
    const int bm = mbase + blockIdx.y * 128;
    const int n0 = blockIdx.x * 128;

    const int lrow = t >> 1;         // 0..127
    const int half = t & 1;          // chunk-group selector
    int mrow = bm + lrow;
    int av = (mrow < mEnd) ? 16 : 0;
    const __half* aRow = A + (size_t)((mrow < mEnd) ? mrow : 0) * K;
    const __half* bRow = B + (size_t)(n0 + lrow) * K;
    const uint32_t aDst = sbase + lrow * 128;
    const uint32_t bDst = sbase + 16384 + lrow * 128;

    float acc[4][4][4];
#pragma unroll
    for (int i = 0; i < 4; i++)
#pragma unroll
        for (int j = 0; j < 4; j++)
#pragma unroll
            for (int q = 0; q < 4; q++) acc[i][j][q] = 0.f;

    auto load_stage = [&](int s, int kt) {
        uint32_t so = (uint32_t)s * STG;
        // 8 chunks of 16B per row span k 0..63; each half-thread does 4
#pragma unroll
        for (int c = 0; c < 4; c++) {
            int chunk = half * 4 + c;
            uint32_t sw = (uint32_t)((chunk ^ (lrow & 7)) << 4);
            cp16(aDst + so + sw, aRow + kt * 64 + chunk * 8, av);
            cp16(bDst + so + sw, bRow + kt * 64 + chunk * 8, 16);
        }
    };

    auto compute = [&](int s) {
        uint32_t aB = sbase + (uint32_t)s * STG;
        uint32_t bB = aB + 16384;
#pragma unroll
        for (int ks = 0; ks < 4; ks++) {          // 4 x k16 per BK=64 stage
            uint32_t Af[4][4];
#pragma unroll
            for (int im = 0; im < 4; im++) {
                int row = wm + im * 16 + (l & 15);
                int ch = ks * 2 + (l >> 4);
                LDSM4(Af[im], aB + row * 128 + ((ch ^ (row & 7)) << 4));
            }
            uint32_t Bf[4][2];
#pragma unroll
            for (int p = 0; p < 2; p++) {
                int row = wn + p * 16 + (l & 7) + ((l >> 4) & 1) * 8;
                int ch = ks * 2 + ((l >> 3) & 1);
                uint32_t r4[4];
                LDSM4(r4, bB + row * 128 + ((ch ^ (row & 7)) << 4));
                Bf[p * 2][0] = r4[0]; Bf[p * 2][1] = r4[1];
                Bf[p * 2 + 1][0] = r4[2]; Bf[p * 2 + 1][1] = r4[3];
            }
#pragma unroll
            for (int im = 0; im < 4; im++)
#pragma unroll
                for (int in = 0; in < 4; in++)
                    MMA16816H(acc[im][in], Af[im], Bf[in]);
        }
    };

    const int KT = K / 64;
    load_stage(0, 0); CP_COMMIT();
    load_stage(1, 1); CP_COMMIT();
    int s = 0;
    for (int kt = 0; kt < KT; kt++) {
        if (kt < KT - 1) { CP_WAIT(1); } else { CP_WAIT(0); }
        __syncthreads();
        if (kt + 2 < KT) {
            int s2 = s + 2; if (s2 >= 3) s2 -= 3;
            load_stage(s2, kt + 2);
            CP_COMMIT();
        }
        compute(s);
        if (++s == 3) s = 0;
    }

#pragma unroll
    for (int im = 0; im < 4; im++) {
        int r0 = bm + wm + im * 16 + (l >> 2);
#pragma unroll
        for (int in = 0; in < 4; in++) {
            int cc = n0 + wn + in * 8 + (l & 3) * 2;
            float* a4 = acc[im][in];
            if (relu) {
                a4[0] = fmaxf(a4[0], 0.f); a4[1] = fmaxf(a4[1], 0.f);
                a4[2] = fmaxf(a4[2], 0.f); a4[3] = fmaxf(a4[3], 0.f);
            }
            if (r0 < mEnd)
                *(float2*)(C + (size_t)r0 * N + cc) = make_float2(a4[0], a4[1]);
            if (r0 + 8 < mEnd)
                *(float2*)(C + (size_t)(r0 + 8) * N + cc) = make_float2(a4[2], a4[3]);
        }
    }
}

// ------------------------ fused attention aggregation (single pass) ----------
__global__ __launch_bounds__(256)
void agg_kernel(const float* __restrict__ S, int nbase, int nEnd) {
    int w = threadIdx.x >> 5;
    int l = threadIdx.x & 31;
    int i = nbase + blockIdx.x * 8 + w;
    if (i >= nEnd) return;

    for (int r = 0; r < 3; r++) {
        float4 acc0 = make_float4(0.f, 0.f, 0.f, 0.f);
        float4 acc1 = make_float4(0.f, 0.f, 0.f, 0.f);
        int start = g_rs[r * (NN + 1) + i];
        int deg   = g_rs[r * (NN + 1) + i + 1] - start;

        if (deg > 0) {
            const float* Pb = g_P + (size_t)i * NP + r * 256;
            float4 p0 = *(const float4*)(Pb + 4 * l);
            float4 p1 = *(const float4*)(Pb + 128 + 4 * l);
            const int* nb = g_snbr + r * 2 * EE + start;

            float z = 0.f;
            for (int j = 0; j < deg; j++) {
                int nbr = nb[j];
                const float* Sr = S + (size_t)nbr * DD;
                float4 s0 = *(const float4*)(Sr + 4 * l);
                float4 s1 = *(const float4*)(Sr + 128 + 4 * l);
                float d = p0.x * s0.x + p0.y * s0.y + p0.z * s0.z + p0.w * s0.w
                        + p1.x * s1.x + p1.y * s1.y + p1.z * s1.z + p1.w * s1.w;
#pragma unroll
                for (int off = 16; off; off >>= 1)
                    d += __shfl_xor_sync(0xFFFFFFFFu, d, off);
                float e = __expf(d * 0.125f);
                z += e;
                acc0.x += e * s0.x; acc0.y += e * s0.y;
                acc0.z += e * s0.z; acc0.w += e * s0.w;
                acc1.x += e * s1.x; acc1.y += e * s1.y;
                acc1.z += e * s1.z; acc1.w += e * s1.w;
            }
            float zi = 1.f / z;
            acc0.x *= zi; acc0.y *= zi; acc0.z *= zi; acc0.w *= zi;
            acc1.x *= zi; acc1.y *= zi; acc1.z *= zi; acc1.w *= zi;
        }
        size_t base = (size_t)i * NP + r * 256;
        cvt4h(acc0, g_Th + base + 4 * l);
        cvt4h(acc1, g_Th + base + 128 + 4 * l);
    }
}

// ------------------------ launch --------------------------------------------
extern "C" void kernel_launch(void* const* d_in, const int* in_sizes, int n_in,
                              void* d_out, int out_size) {
    const float* S  = (const float*)d_in[0];
    const int*   et = (const int*)d_in[1];
    const int*   ec = (const int*)d_in[2];
    const int*   e2 = (const int*)d_in[3];
    const float* W  = (const float*)d_in[4];
    const float* WQ = (const float*)d_in[5];
    const float* WK = (const float*)d_in[6];
    float* out = (float*)d_out;

    static bool init = false;
    static __half *pSh, *pWah, *pWvh, *pTh;
    static float* pP;
    static cudaStream_t s1, s2, s3;
    static cudaEvent_t evFork, evCSR, evW, evG1a, evG1b, evAa, evAb;
    if (!init) {
        cudaGetSymbolAddress((void**)&pSh,  g_Sh);
        cudaGetSymbolAddress((void**)&pWah, g_Wah);
        cudaGetSymbolAddress((void**)&pWvh, g_Wvh);
        cudaGetSymbolAddress((void**)&pTh,  g_Th);
        cudaGetSymbolAddress((void**)&pP,   g_P);
        cudaFuncSetAttribute(mma_gemm, cudaFuncAttributeMaxDynamicSharedMemorySize,
                             GEMM_SMEM);
        cudaStreamCreateWithFlags(&s1, cudaStreamNonBlocking);
        cudaStreamCreateWithFlags(&s2, cudaStreamNonBlocking);
        cudaStreamCreateWithFlags(&s3, cudaStreamNonBlocking);
        cudaEventCreateWithFlags(&evFork, cudaEventDisableTiming);
        cudaEventCreateWithFlags(&evCSR,  cudaEventDisableTiming);
        cudaEventCreateWithFlags(&evW,    cudaEventDisableTiming);
        cudaEventCreateWithFlags(&evG1a,  cudaEventDisableTiming);
        cudaEventCreateWithFlags(&evG1b,  cudaEventDisableTiming);
        cudaEventCreateWithFlags(&evAa,   cudaEventDisableTiming);
        cudaEventCreateWithFlags(&evAb,   cudaEventDisableTiming);
        init = true;
    }

    const int MB_A = MSPLIT / 128;                 // 196
    const int MB_B = (NN - MSPLIT + 127) / 128;    // 195
    const int NB_A = (MSPLIT + 7) / 8;
    const int NB_B = (NN - MSPLIT + 7) / 8;

    // fork
    cudaEventRecord(evFork, 0);
    cudaStreamWaitEvent(s1, evFork, 0);
    cudaStreamWaitEvent(s2, evFork, 0);
    cudaStreamWaitEvent(s3, evFork, 0);

    // s1: CSR build chain
    zero_kernel<<<(3 * NN + 255) / 256, 256, 0, s1>>>();
    degree_kernel<<<(3 * 2 * EE + 255) / 256, 256, 0, s1>>>(et, ec, e2);
    scan_local<<<dim3(SCAN_BLOCKS, 3), 1024, 0, s1>>>();
    scan_bsums<<<1, 96, 0, s1>>>();
    scan_add<<<dim3(SCAN_BLOCKS, 3), 1024, 0, s1>>>();
    fill_kernel<<<(3 * EE + 255) / 256, 256, 0, s1>>>(et, ec, e2);
    cudaEventRecord(evCSR, s1);

    // s2: weight prep
    build_wa<<<NP, 256, 0, s2>>>(WQ, WK);
    build_wv<<<(DD * NP + 255) / 256, 256, 0, s2>>>(W);
    cudaEventRecord(evW, s2);

    // main: convert S, then GEMM1 in two M-slices
    convertS_kernel<<<(NN * DD / 4 + 255) / 256, 256>>>(S);
    cudaStreamWaitEvent(0, evW, 0);
    mma_gemm<<<dim3(NP / 128, MB_A), 256, GEMM_SMEM>>>(
        pSh, pWah, pP, 0, MSPLIT, DD, NP, 0);
    cudaEventRecord(evG1a, 0);
    mma_gemm<<<dim3(NP / 128, MB_B), 256, GEMM_SMEM>>>(
        pSh, pWah, pP, MSPLIT, NN, DD, NP, 0);
    cudaEventRecord(evG1b, 0);

    // s3: agg slices (overlap with GEMM1b / GEMM2a)
    cudaStreamWaitEvent(s3, evCSR, 0);
    cudaStreamWaitEvent(s3, evG1a, 0);
    agg_kernel<<<NB_A, 256, 0, s3>>>(S, 0, MSPLIT);
    cudaEventRecord(evAa, s3);
    cudaStreamWaitEvent(s3, evG1b, 0);
    agg_kernel<<<NB_B, 256, 0, s3>>>(S, MSPLIT, NN);
    cudaEventRecord(evAb, s3);

    // main: GEMM2 slices (relu fused)
    cudaStreamWaitEvent(0, evAa, 0);
    mma_gemm<<<dim3(DD / 128, MB_A), 256, GEMM_SMEM>>>(
        pTh, pWvh, out, 0, MSPLIT, NP, DD, 1);
    cudaStreamWaitEvent(0, evAb, 0);
    mma_gemm<<<dim3(DD / 128, MB_B), 256, GEMM_SMEM>>>(
        pTh, pWvh, out, MSPLIT, NN, NP, DD, 1);
}